// round 3
// baseline (speedup 1.0000x reference)
#include <cuda_runtime.h>
#include <cuda_bf16.h>

// Problem constants (match reference_code)
#define Bv     32768
#define LMAXv  24
#define Mv     10
#define Dv     300
#define Vv     36
#define D4     75            // D / 4 (float4 chunks per row)
#define ROW4   (Mv * D4)     // 750 float4 per batch element

__device__ __forceinline__ float4 lerp4(float4 a, float4 b, float w, float omw) {
    float4 r;
    r.x = a.x * omw + b.x * w;
    r.y = a.y * omw + b.y * w;
    r.z = a.z * omw + b.z * w;
    r.w = a.w * omw + b.w * w;
    return r;
}

__device__ __forceinline__ float4 body(int j,
                                       const int*   s_olo,
                                       const int*   s_ohi,
                                       const float* s_w,
                                       const float4* __restrict__ embv,
                                       const float4* __restrict__ padv)
{
    const int m = j / D4;              // const divisor -> mul/shift
    const int c = j - m * D4;
    const int olo = s_olo[m];
    if (olo < 0) return __ldg(padv + c);
    const float w = s_w[m];
    float4 a = __ldg(embv + olo + c);
    if (w == 0.0f) return a;
    float4 b = __ldg(embv + s_ohi[m] + c);
    return lerp4(a, b, w, 1.0f - w);
}

__global__ __launch_bounds__(256, 8)
void word_embed_kernel(const float* __restrict__ emb,     // [V, D]
                       const float* __restrict__ pad,     // [1, D]
                       const int*   __restrict__ tokens,  // [B, LMAX]
                       const int*   __restrict__ lengths, // [B]
                       float*       __restrict__ out)     // [B, M, D]
{
    const int b   = blockIdx.x;
    const int tid = threadIdx.x;

    __shared__ int   s_olo[Mv];   // precomputed float4 offset of lo row (or -1 => pad)
    __shared__ int   s_ohi[Mv];   // precomputed float4 offset of hi row
    __shared__ float s_w[Mv];     // interp weight

    const int L = __ldg(lengths + b);
    const int* tokrow = tokens + b * LMAXv;

    if (tid < Mv) {
        const int m = tid;
        if (L < Mv) {
            // padding branch: first L rows are embeddings, rest is pad vector
            if (m < L) {
                int t = __ldg(tokrow + m);
                s_olo[m] = t * D4; s_ohi[m] = t * D4; s_w[m] = 0.0f;
            } else {
                s_olo[m] = -1; s_ohi[m] = -1; s_w[m] = 0.0f;
            }
        } else {
            // interpolate branch: src = m * (L-1) / (M-1), align_corners=True
            float pos = (float)m * (float)(L - 1) / (float)(Mv - 1);
            int   lo  = (int)floorf(pos);
            int   hi  = min(lo + 1, L - 1);
            float w   = pos - (float)lo;
            s_olo[m] = __ldg(tokrow + lo) * D4;
            s_ohi[m] = __ldg(tokrow + hi) * D4;
            s_w[m]   = w;
        }
    }
    __syncthreads();

    const float4* __restrict__ embv = (const float4*)emb;
    const float4* __restrict__ padv = (const float4*)pad;
    float4* __restrict__ outv = (float4*)out + (size_t)b * ROW4;

    // ROW4 = 750 = 2*256 + 238: two full strides + one partial.
    const int j0 = tid;
    const int j1 = tid + 256;
    const int j2 = tid + 512;

    float4 r0 = body(j0, s_olo, s_ohi, s_w, embv, padv);
    float4 r1 = body(j1, s_olo, s_ohi, s_w, embv, padv);
    outv[j0] = r0;
    outv[j1] = r1;
    if (j2 < ROW4) {
        float4 r2 = body(j2, s_olo, s_ohi, s_w, embv, padv);
        outv[j2] = r2;
    }
}

extern "C" void kernel_launch(void* const* d_in, const int* in_sizes, int n_in,
                              void* d_out, int out_size)
{
    const float* emb     = (const float*)d_in[0];   // [36, 300]
    const float* pad     = (const float*)d_in[1];   // [1, 300]
    const int*   tokens  = (const int*)d_in[2];     // [32768, 24]
    const int*   lengths = (const int*)d_in[3];     // [32768]
    float*       out     = (float*)d_out;           // [32768, 10, 300]

    word_embed_kernel<<<Bv, 256>>>(emb, pad, tokens, lengths, out);
}

// round 5
// speedup vs baseline: 1.2965x; 1.2965x over previous
#include <cuda_runtime.h>
#include <cuda_bf16.h>

// Problem constants (match reference_code)
#define Bv     32768
#define LMAXv  24
#define Mv     10
#define Dv     300
#define Vv     36
#define D4     75            // D / 4 (float4 chunks per row)
#define ROW4   (Mv * D4)     // 750 float4 per batch element

__global__ __launch_bounds__(256, 8)
void word_embed_kernel(const float* __restrict__ emb,     // [V, D]
                       const float* __restrict__ pad,     // [1, D]
                       const int*   __restrict__ tokens,  // [B, LMAX]
                       const int*   __restrict__ lengths, // [B]
                       float*       __restrict__ out)     // [B, M, D]
{
    const int b   = blockIdx.x;
    const int tid = threadIdx.x;

    // Per-m descriptors: lo/hi row pointers (pad folded in) + weight.
    __shared__ const float4* s_lo[Mv];
    __shared__ const float4* s_hi[Mv];
    __shared__ float         s_w[Mv];

    const int L = __ldg(lengths + b);
    const int* tokrow = tokens + b * LMAXv;
    const float4* __restrict__ embv = (const float4*)emb;
    const float4* __restrict__ padv = (const float4*)pad;

    if (tid < Mv) {
        const int m = tid;
        if (L < Mv) {
            if (m < L) {
                const float4* p = embv + __ldg(tokrow + m) * D4;
                s_lo[m] = p; s_hi[m] = p; s_w[m] = 0.0f;
            } else {
                s_lo[m] = padv; s_hi[m] = padv; s_w[m] = 0.0f;
            }
        } else {
            // interpolate branch: src = m * (L-1) / (M-1), align_corners=True
            float pos = (float)m * (float)(L - 1) / (float)(Mv - 1);
            int   lo  = (int)floorf(pos);
            int   hi  = min(lo + 1, L - 1);
            s_lo[m] = embv + __ldg(tokrow + lo) * D4;
            s_hi[m] = embv + __ldg(tokrow + hi) * D4;
            s_w[m]  = pos - (float)lo;
        }
    }
    __syncthreads();

    // ROW4 = 750 = 2*256 + 238: two full strides + one partial (predicated store).
    const int j0 = tid;
    const int j1 = tid + 256;
    const int j2t = tid + 512;
    const bool p2 = (j2t < ROW4);
    const int j2 = p2 ? j2t : (ROW4 - 1);   // clamp: keeps smem/table reads in-bounds

    const int m0 = j0 / D4, c0 = j0 - m0 * D4;
    const int m1 = j1 / D4, c1 = j1 - m1 * D4;
    const int m2 = j2 / D4, c2 = j2 - m2 * D4;

    const float4* plo0 = s_lo[m0] + c0;  const float4* phi0 = s_hi[m0] + c0;  const float w0 = s_w[m0];
    const float4* plo1 = s_lo[m1] + c1;  const float4* phi1 = s_hi[m1] + c1;  const float w1 = s_w[m1];
    const float4* plo2 = s_lo[m2] + c2;  const float4* phi2 = s_hi[m2] + c2;  const float w2 = s_w[m2];

    // Front-batch all lo-loads, then predicated hi-loads -> MLP ~6.
    float4 a0 = __ldg(plo0);
    float4 a1 = __ldg(plo1);
    float4 a2 = __ldg(plo2);
    float4 b0 = (w0 != 0.0f) ? __ldg(phi0) : a0;
    float4 b1 = (w1 != 0.0f) ? __ldg(phi1) : a1;
    float4 b2 = (w2 != 0.0f) ? __ldg(phi2) : a2;

    const float o0 = 1.0f - w0, o1 = 1.0f - w1, o2 = 1.0f - w2;
    float4 r0, r1, r2;
    r0.x = a0.x * o0 + b0.x * w0;  r0.y = a0.y * o0 + b0.y * w0;
    r0.z = a0.z * o0 + b0.z * w0;  r0.w = a0.w * o0 + b0.w * w0;
    r1.x = a1.x * o1 + b1.x * w1;  r1.y = a1.y * o1 + b1.y * w1;
    r1.z = a1.z * o1 + b1.z * w1;  r1.w = a1.w * o1 + b1.w * w1;
    r2.x = a2.x * o2 + b2.x * w2;  r2.y = a2.y * o2 + b2.y * w2;
    r2.z = a2.z * o2 + b2.z * w2;  r2.w = a2.w * o2 + b2.w * w2;

    float4* __restrict__ outv = (float4*)out + (size_t)b * ROW4;
    outv[j0] = r0;
    outv[j1] = r1;
    if (p2) outv[j2t] = r2;
}

extern "C" void kernel_launch(void* const* d_in, const int* in_sizes, int n_in,
                              void* d_out, int out_size)
{
    const float* emb     = (const float*)d_in[0];   // [36, 300]
    const float* pad     = (const float*)d_in[1];   // [1, 300]
    const int*   tokens  = (const int*)d_in[2];     // [32768, 24]
    const int*   lengths = (const int*)d_in[3];     // [32768]
    float*       out     = (float*)d_out;           // [32768, 10, 300]

    word_embed_kernel<<<Bv, 256>>>(emb, pad, tokens, lengths, out);
}